// round 7
// baseline (speedup 1.0000x reference)
#include <cuda_runtime.h>
#include <cuda_bf16.h>
#include <math.h>
#include <cstdint>

#define NN 20000
#define NE 320000
#define D  128
#define H  12
#define HO 1536          // H * D
#define BN_EPS 1e-5f
#define MPAD 20096       // 157 * 128
#define KT 384           // 3 * 128 (bf16 double-split emulated fp32 GEMM)

// mma_y smem geometry: rows of 72 bf16 (144 B) -> LDSM conflict-free
#define ROWB   144
#define ATILE  (128 * ROWB)          // 18432 B
#define BUFB   (2 * ATILE)           // 36864 B (A + B)
#define SMEM_DYN (2 * BUFB)          // 73728 B double buffered

typedef unsigned long long u64;
typedef uint32_t u32;

// ---------------- packed f32x2 helpers --------------------------------------
__device__ __forceinline__ u64 pack2(float lo, float hi) {
    u64 r; asm("mov.b64 %0, {%1,%2};" : "=l"(r) : "f"(lo), "f"(hi)); return r;
}
__device__ __forceinline__ u64 ffma2(u64 a, u64 b, u64 c) {
    u64 d; asm("fma.rn.f32x2 %0, %1, %2, %3;" : "=l"(d) : "l"(a), "l"(b), "l"(c)); return d;
}
__device__ __forceinline__ void unpack2(u64 v, float& lo, float& hi) {
    asm("mov.b64 {%0,%1}, %2;" : "=f"(lo), "=f"(hi) : "l"(v));
}
__device__ __forceinline__ void red_add_v4(float* p, float a, float b, float c, float d) {
    asm volatile("red.global.add.v4.f32 [%0], {%1,%2,%3,%4};"
                 :: "l"(p), "f"(a), "f"(b), "f"(c), "f"(d) : "memory");
}
union F4U { float4 f; u64 u[2]; };

// ---------------- mma building blocks ---------------------------------------
__device__ __forceinline__ u32 smem_u32(const void* p) {
    u32 a;
    asm("{ .reg .u64 t; cvta.to.shared.u64 t, %1; cvt.u32.u64 %0, t; }" : "=r"(a) : "l"(p));
    return a;
}
__device__ __forceinline__ void cp16(u32 saddr, const void* g) {
    asm volatile("cp.async.cg.shared.global [%0], [%1], 16;" :: "r"(saddr), "l"(g));
}
__device__ __forceinline__ void ldsm4(u32& r0, u32& r1, u32& r2, u32& r3, u32 addr) {
    asm volatile("ldmatrix.sync.aligned.m8n8.x4.shared.b16 {%0,%1,%2,%3}, [%4];"
                 : "=r"(r0), "=r"(r1), "=r"(r2), "=r"(r3) : "r"(addr));
}

// ---------------- scratch (device globals) ----------------------------------
__device__ __nv_bfloat16 g_Abig[(size_t)MPAD * KT];   // [row, 384] = [hi|hi|lo]
__device__ __nv_bfloat16 g_Bbig[(size_t)HO * KT];     // [out, 384] = [hi|lo|hi]
__device__ float g_Y[(size_t)NN * HO];
__device__ float g_U[NN * H];
__device__ float g_t[NN * D];
__device__ float g_h[NN * D];
__device__ float g_agg[NN * D];
__device__ int   g_deg[NN];
__device__ float g_sum[D];
__device__ float g_sumsq[D];
__device__ int   g_rowptr[NN + 1];
__device__ int   g_cnt[NN];
__device__ int   g_adj[NE];

// ---------------- degree / CSR (built once) ---------------------------------
__global__ void deg_init_kernel() {
    int i = blockIdx.x * blockDim.x + threadIdx.x;
    if (i < NN) g_deg[i] = 1;
}
__global__ void deg_count_kernel(const int* __restrict__ ei) {
    int e = blockIdx.x * blockDim.x + threadIdx.x;
    if (e < NE) atomicAdd(&g_deg[ei[NE + e]], 1);
}
__global__ void csr_zero_kernel() {
    int i = blockIdx.x * blockDim.x + threadIdx.x;
    if (i < NN) g_cnt[i] = 0;
}
__global__ void csr_count_kernel(const int* __restrict__ ei) {
    int e = blockIdx.x * blockDim.x + threadIdx.x;
    if (e < NE) atomicAdd(&g_cnt[ei[e]], 1);
}
__global__ void csr_scan_kernel() {
    __shared__ int sh[1024];
    __shared__ int carry;
    if (threadIdx.x == 0) { carry = 0; g_rowptr[0] = 0; }
    __syncthreads();
    for (int base = 0; base < NN; base += 1024) {
        int i = base + threadIdx.x;
        int v = (i < NN) ? g_cnt[i] : 0;
        sh[threadIdx.x] = v;
        __syncthreads();
        for (int o = 1; o < 1024; o <<= 1) {
            int t = (threadIdx.x >= o) ? sh[threadIdx.x - o] : 0;
            __syncthreads();
            sh[threadIdx.x] += t;
            __syncthreads();
        }
        int base_off = carry;
        __syncthreads();
        if (i < NN) g_rowptr[i + 1] = base_off + sh[threadIdx.x];
        __syncthreads();
        if (threadIdx.x == 0) carry = base_off + sh[1023];
        __syncthreads();
    }
}
__global__ void csr_fill_kernel(const int* __restrict__ ei) {
    int e = blockIdx.x * blockDim.x + threadIdx.x;
    if (e >= NE) return;
    int s = ei[e];
    int pos = atomicAdd(&g_cnt[s], 1);
    g_adj[g_rowptr[s] + pos] = ei[NE + e];
}

// ---------------- zero agg + bn accumulators --------------------------------
__global__ void zero_kernel() {
    int i = blockIdx.x * blockDim.x + threadIdx.x;
    if (i < NN * D) g_agg[i] = 0.f;
    if (i < D) { g_sum[i] = 0.f; g_sumsq[i] = 0.f; }
}

// ---------------- input converts (bf16 double split) ------------------------
__global__ void convertx_kernel(const float* __restrict__ X) {
    int i = blockIdx.x * blockDim.x + threadIdx.x;
    if (i >= MPAD * D) return;
    int n = i >> 7, c = i & 127;
    float v = (n < NN) ? X[i] : 0.f;
    __nv_bfloat16 hi = __float2bfloat16(v);
    __nv_bfloat16 lo = __float2bfloat16(v - __bfloat162float(hi));
    size_t base = (size_t)n * KT + c;
    g_Abig[base]       = hi;
    g_Abig[base + 128] = hi;
    g_Abig[base + 256] = lo;
}
// fused BN apply + split convert (also emits fp32 g_h for u_kernel)
__global__ void bnconvert_kernel(const float* __restrict__ t,
                                 const float* __restrict__ gam,
                                 const float* __restrict__ bet) {
    int i = blockIdx.x * blockDim.x + threadIdx.x;
    if (i >= MPAD * D) return;
    int n = i >> 7, c = i & 127;
    float v = 0.f;
    if (n < NN) {
        const float invN = 1.f / (float)NN;
        float m  = g_sum[c] * invN;
        float vr = g_sumsq[c] * invN - m * m;
        v = (t[i] - m) * rsqrtf(vr + BN_EPS) * gam[c] + bet[c];
        g_h[i] = v;
    }
    __nv_bfloat16 hi = __float2bfloat16(v);
    __nv_bfloat16 lo = __float2bfloat16(v - __bfloat162float(hi));
    size_t base = (size_t)n * KT + c;
    g_Abig[base]       = hi;
    g_Abig[base + 128] = hi;
    g_Abig[base + 256] = lo;
}
__global__ void convertw_kernel(const float* __restrict__ W) {
    int i = blockIdx.x * blockDim.x + threadIdx.x;
    if (i >= HO * D) return;
    int o = i >> 7, c = i & 127;
    float v = W[i];
    __nv_bfloat16 hi = __float2bfloat16(v);
    __nv_bfloat16 lo = __float2bfloat16(v - __bfloat162float(hi));
    size_t base = (size_t)o * KT + c;
    g_Bbig[base]       = hi;
    g_Bbig[base + 128] = lo;
    g_Bbig[base + 256] = hi;
}

// ---------------- mma.sync GEMM: Y[m,o] = sum_k Abig[m,k]*Bbig[o,k] ---------
// grid (12, 157), 128 threads (4 warps, 2x2, warp tile 64x64).
// CTA tile M=128 N=128, K=384 in 6 chunks of 64, cp.async double-buffered.
__global__ __launch_bounds__(128) void mma_y_kernel() {
    extern __shared__ char smem[];
    const int tid  = threadIdx.x;
    const int wid  = tid >> 5, lane = tid & 31;
    const int wm   = (wid >> 1) * 64;
    const int wn   = (wid & 1) * 64;
    const int bm   = blockIdx.y * 128;
    const int bo   = blockIdx.x * 128;
    const int g    = lane >> 2;
    const int tq   = lane & 3;

    const u32 sb = smem_u32(smem);

    float acc[4][8][4];
#pragma unroll
    for (int i = 0; i < 4; i++)
#pragma unroll
        for (int j = 0; j < 8; j++)
#pragma unroll
            for (int q = 0; q < 4; q++) acc[i][j][q] = 0.f;

    // one thread per tile row (128 threads = 128 rows); 8x16B per matrix per chunk
    const char* gA = (const char*)g_Abig + (size_t)(bm + tid) * (KT * 2);
    const char* gB = (const char*)g_Bbig + (size_t)(bo + tid) * (KT * 2);
    const u32 sA = sb + tid * ROWB;
    const u32 sBo = sb + ATILE + tid * ROWB;

    // prologue: chunk 0 -> buffer 0
#pragma unroll
    for (int j = 0; j < 8; j++) {
        cp16(sA  + j * 16, gA + j * 16);
        cp16(sBo + j * 16, gB + j * 16);
    }
    asm volatile("cp.async.commit_group;");

    // precompute per-warp ldmatrix lane addressing
    const int a_row = wm + (lane & 15);
    const int a_kb  = (lane >> 4) * 16;          // bytes: +0 / +16
    const int b_t   = lane >> 3;
    const int b_row = wn + ((b_t >> 1) * 8) + (lane & 7);
    const int b_kb  = (b_t & 1) * 16;            // bytes

    for (int ch = 0; ch < 6; ch++) {
        if (ch < 5) {
            const u32 base = ((ch + 1) & 1) * BUFB;
            const int off = (ch + 1) * 128;
#pragma unroll
            for (int j = 0; j < 8; j++) {
                cp16(sb + base + tid * ROWB + j * 16,         gA + off + j * 16);
                cp16(sb + base + ATILE + tid * ROWB + j * 16, gB + off + j * 16);
            }
            asm volatile("cp.async.commit_group;");
            asm volatile("cp.async.wait_group 1;");
        } else {
            asm volatile("cp.async.wait_group 0;");
        }
        __syncthreads();

        const u32 Ab = sb + (ch & 1) * BUFB;
        const u32 Bb = Ab + ATILE;
#pragma unroll
        for (int k = 0; k < 4; k++) {
            const int kb = k * 32;               // 16 bf16 = 32 bytes
            u32 a[4][4], b[4][4];
#pragma unroll
            for (int i = 0; i < 4; i++)
                ldsm4(a[i][0], a[i][1], a[i][2], a[i][3],
                      Ab + (a_row + i * 16) * ROWB + kb + a_kb);
#pragma unroll
            for (int jj = 0; jj < 4; jj++)
                ldsm4(b[jj][0], b[jj][1], b[jj][2], b[jj][3],
                      Bb + (b_row + jj * 16) * ROWB + kb + b_kb);
#pragma unroll
            for (int i = 0; i < 4; i++)
#pragma unroll
                for (int j = 0; j < 8; j++) {
                    const u32 b0 = b[j >> 1][(j & 1) * 2];
                    const u32 b1 = b[j >> 1][(j & 1) * 2 + 1];
                    asm volatile(
                        "mma.sync.aligned.m16n8k16.row.col.f32.bf16.bf16.f32 "
                        "{%0,%1,%2,%3}, {%4,%5,%6,%7}, {%8,%9}, {%0,%1,%2,%3};"
                        : "+f"(acc[i][j][0]), "+f"(acc[i][j][1]),
                          "+f"(acc[i][j][2]), "+f"(acc[i][j][3])
                        : "r"(a[i][0]), "r"(a[i][1]), "r"(a[i][2]), "r"(a[i][3]),
                          "r"(b0), "r"(b1));
                }
        }
        __syncthreads();
    }

    // epilogue
#pragma unroll
    for (int i = 0; i < 4; i++) {
        int r0 = bm + wm + i * 16 + g;
        int r1 = r0 + 8;
#pragma unroll
        for (int j = 0; j < 8; j++) {
            int col = bo + wn + j * 8 + tq * 2;
            if (r0 < NN)
                *(float2*)(g_Y + (size_t)r0 * HO + col) = make_float2(acc[i][j][0], acc[i][j][1]);
            if (r1 < NN)
                *(float2*)(g_Y + (size_t)r1 * HO + col) = make_float2(acc[i][j][2], acc[i][j][3]);
        }
    }
}

// ---------------- U[n,h] = sum_k X[n,k]*Wu[h,k]  (warp per node) ------------
__global__ void u_kernel(const float* __restrict__ X, const float* __restrict__ Wu, int M) {
    __shared__ float wu[H * D];
    for (int i = threadIdx.x; i < H * D; i += blockDim.x) wu[i] = Wu[i];
    __syncthreads();
    int warp = blockIdx.x * (blockDim.x >> 5) + (threadIdx.x >> 5);
    int lane = threadIdx.x & 31;
    if (warp >= M) return;
    const float* xr = X + (size_t)warp * D;
    float x0 = xr[lane], x1 = xr[lane + 32], x2 = xr[lane + 64], x3 = xr[lane + 96];
#pragma unroll
    for (int h = 0; h < H; h++) {
        float p = x0 * wu[h * D + lane] + x1 * wu[h * D + lane + 32]
                + x2 * wu[h * D + lane + 64] + x3 * wu[h * D + lane + 96];
#pragma unroll
        for (int o = 16; o; o >>= 1) p += __shfl_xor_sync(0xffffffffu, p, o);
        if (lane == 0) g_U[warp * H + h] = p;
    }
}

// ---------------- scatter: warp per SRC node, Y row in registers ------------
__global__ __launch_bounds__(256) void scatter_kernel(const float* __restrict__ cvec) {
    int warp = blockIdx.x * 8 + (threadIdx.x >> 5);
    int lane = threadIdx.x & 31;
    if (warp >= NN) return;
    const int s = warp;

    F4U yv[H];
    const float4* y4 = reinterpret_cast<const float4*>(g_Y + (size_t)s * HO) + lane;
#pragma unroll
    for (int h = 0; h < H; h++) yv[h].f = y4[h * 32];

    float us = 0.f, cl = 0.f;
    if (lane < H) { us = g_U[s * H + lane]; cl = __ldg(&cvec[lane]); }

    int row = g_rowptr[s], end = g_rowptr[s + 1];
    for (int i = row - 1; i < end; i++) {     // i == row-1 encodes the self loop
        int d = s;
        float ud = us;
        if (i >= row) {
            d = g_adj[i];
            ud = (lane < H) ? __ldg(&g_U[d * H + lane]) : 0.f;
        }
        float logit = (lane < H) ? (ud - us + cl) : -1e30f;
        float m = logit;
#pragma unroll
        for (int o = 16; o; o >>= 1) m = fmaxf(m, __shfl_xor_sync(0xffffffffu, m, o));
        float e = (lane < H) ? __expf(logit - m) : 0.f;
        float ss = e;
#pragma unroll
        for (int o = 16; o; o >>= 1) ss += __shfl_xor_sync(0xffffffffu, ss, o);
        float a = e / ss;

        u64 m0 = 0ull, m1 = 0ull;
#pragma unroll
        for (int h = 0; h < H; h++) {
            float ah = __shfl_sync(0xffffffffu, a, h);
            u64 a2 = pack2(ah, ah);
            m0 = ffma2(a2, yv[h].u[0], m0);
            m1 = ffma2(a2, yv[h].u[1], m1);
        }
        float r0, r1, r2, r3;
        unpack2(m0, r0, r1);
        unpack2(m1, r2, r3);
        red_add_v4(g_agg + (size_t)d * D + lane * 4, r0, r1, r2, r3);
    }
}

// ---------------- finalize: out = agg/deg + b (+relu, + BN stats) -----------
__global__ __launch_bounds__(256) void finalize_kernel(const float* __restrict__ bvec,
                                                       float* __restrict__ out,
                                                       int relu, int do_stats) {
    int c = threadIdx.x & 127;
    float bb = __ldg(&bvec[c]);
    float lsum = 0.f, lsq = 0.f;
    for (int i = blockIdx.x * blockDim.x + threadIdx.x; i < NN * D;
         i += gridDim.x * blockDim.x) {
        float v = g_agg[i] / (float)g_deg[i >> 7] + bb;
        if (relu) v = fmaxf(v, 0.f);
        out[i] = v;
        lsum += v; lsq += v * v;
    }
    if (do_stats) {
        __shared__ float s1[256], s2[256];
        s1[threadIdx.x] = lsum; s2[threadIdx.x] = lsq;
        __syncthreads();
        if (threadIdx.x < 128) {
            atomicAdd(&g_sum[threadIdx.x],   s1[threadIdx.x] + s1[threadIdx.x + 128]);
            atomicAdd(&g_sumsq[threadIdx.x], s2[threadIdx.x] + s2[threadIdx.x + 128]);
        }
    }
}

// ---------------- launch ----------------------------------------------------
static void launch_mma() {
    cudaFuncSetAttribute(mma_y_kernel, cudaFuncAttributeMaxDynamicSharedMemorySize, SMEM_DYN);
    mma_y_kernel<<<dim3(12, 157), 128, SMEM_DYN>>>();
}

extern "C" void kernel_launch(void* const* d_in, const int* in_sizes, int n_in,
                              void* d_out, int out_size)
{
    const float* x  = (const float*)d_in[0];
    const int*   ei = (const int*)d_in[1];

    const float *Wlin[3], *Wu[3], *cv[3], *bv[3], *bng[2], *bnb[2];
    if (in_sizes[6] == H * D * D) {
        for (int l = 0; l < 3; l++) {
            Wlin[l] = (const float*)d_in[2 + 4 * l];
            Wu[l]   = (const float*)d_in[3 + 4 * l];
            cv[l]   = (const float*)d_in[4 + 4 * l];
            bv[l]   = (const float*)d_in[5 + 4 * l];
        }
        bng[0] = (const float*)d_in[14]; bnb[0] = (const float*)d_in[15];
        bng[1] = (const float*)d_in[16]; bnb[1] = (const float*)d_in[17];
    } else {
        Wlin[0] = (const float*)d_in[2];  Wu[0] = (const float*)d_in[3];
        cv[0]   = (const float*)d_in[4];  bv[0] = (const float*)d_in[5];
        bng[0]  = (const float*)d_in[6];  bnb[0] = (const float*)d_in[7];
        Wlin[1] = (const float*)d_in[8];  Wu[1] = (const float*)d_in[9];
        cv[1]   = (const float*)d_in[10]; bv[1] = (const float*)d_in[11];
        bng[1]  = (const float*)d_in[12]; bnb[1] = (const float*)d_in[13];
        Wlin[2] = (const float*)d_in[14]; Wu[2] = (const float*)d_in[15];
        cv[2]   = (const float*)d_in[16]; bv[2] = (const float*)d_in[17];
    }

    float* out = (float*)d_out;
    float* t = nullptr; float* hbuf = nullptr;
    cudaGetSymbolAddress((void**)&t, g_t);
    cudaGetSymbolAddress((void**)&hbuf, g_h);

    const int NCONV = (MPAD * D + 255) / 256;
    const int WCONV = (HO * D + 255) / 256;

    // ---- layer 0 front, ordered so launch index 3 == mma_y (ncu -s window) ----
    convertx_kernel<<<NCONV, 256>>>(x);                       // 0
    convertw_kernel<<<WCONV, 256>>>(Wlin[0]);                 // 1
    deg_init_kernel<<<(NN + 255) / 256, 256>>>();             // 2
    launch_mma();                                             // 3  <- profiled
    deg_count_kernel<<<(NE + 255) / 256, 256>>>(ei);
    csr_zero_kernel<<<(NN + 255) / 256, 256>>>();
    csr_count_kernel<<<(NE + 255) / 256, 256>>>(ei);
    csr_scan_kernel<<<1, 1024>>>();
    csr_zero_kernel<<<(NN + 255) / 256, 256>>>();
    csr_fill_kernel<<<(NE + 255) / 256, 256>>>(ei);

    u_kernel<<<(NN * 32 + 255) / 256, 256>>>(x, Wu[0], NN);
    zero_kernel<<<(NN * D + 255) / 256, 256>>>();
    scatter_kernel<<<(NN + 7) / 8, 256>>>(cv[0]);
    finalize_kernel<<<192, 256>>>(bv[0], t, 1, 1);

    // ---- layer 1 (BN0 fused into convert) ----
    bnconvert_kernel<<<NCONV, 256>>>(t, bng[0], bnb[0]);
    convertw_kernel<<<WCONV, 256>>>(Wlin[1]);
    launch_mma();
    u_kernel<<<(NN * 32 + 255) / 256, 256>>>(hbuf, Wu[1], NN);
    zero_kernel<<<(NN * D + 255) / 256, 256>>>();
    scatter_kernel<<<(NN + 7) / 8, 256>>>(cv[1]);
    finalize_kernel<<<192, 256>>>(bv[1], t, 1, 1);

    // ---- layer 2 (BN1 fused; no relu/stats) -> d_out ----
    bnconvert_kernel<<<NCONV, 256>>>(t, bng[1], bnb[1]);
    convertw_kernel<<<WCONV, 256>>>(Wlin[2]);
    launch_mma();
    u_kernel<<<(NN * 32 + 255) / 256, 256>>>(hbuf, Wu[2], NN);
    zero_kernel<<<(NN * D + 255) / 256, 256>>>();
    scatter_kernel<<<(NN + 7) / 8, 256>>>(cv[2]);
    finalize_kernel<<<192, 256>>>(bv[2], out, 0, 0);
}

// round 8
// speedup vs baseline: 1.0638x; 1.0638x over previous
#include <cuda_runtime.h>
#include <cuda_bf16.h>
#include <math.h>
#include <cstdint>

#define NN 20000
#define NE 320000
#define D  128
#define H  12
#define HO 1536          // H * D
#define BN_EPS 1e-5f
#define MPAD 20096       // 157 * 128
#define KT 384           // 3 * 128 (bf16 double-split emulated fp32 GEMM)

// mma_y smem geometry: rows of 72 bf16 (144 B) -> LDSM conflict-free
#define ROWB   144
#define ATILE  (128 * ROWB)          // 18432 B
#define BUFB   (2 * ATILE)           // 36864 B (A + B)
#define SMEM_DYN (2 * BUFB)          // 73728 B double buffered

typedef unsigned long long u64;
typedef uint32_t u32;

// ---------------- packed f32x2 helpers --------------------------------------
__device__ __forceinline__ u64 pack2(float lo, float hi) {
    u64 r; asm("mov.b64 %0, {%1,%2};" : "=l"(r) : "f"(lo), "f"(hi)); return r;
}
__device__ __forceinline__ u64 ffma2(u64 a, u64 b, u64 c) {
    u64 d; asm("fma.rn.f32x2 %0, %1, %2, %3;" : "=l"(d) : "l"(a), "l"(b), "l"(c)); return d;
}
__device__ __forceinline__ void unpack2(u64 v, float& lo, float& hi) {
    asm("mov.b64 {%0,%1}, %2;" : "=f"(lo), "=f"(hi) : "l"(v));
}
__device__ __forceinline__ void red_add_v4(float* p, float a, float b, float c, float d) {
    asm volatile("red.global.add.v4.f32 [%0], {%1,%2,%3,%4};"
                 :: "l"(p), "f"(a), "f"(b), "f"(c), "f"(d) : "memory");
}
union F4U { float4 f; u64 u[2]; };

// ---------------- mma building blocks ---------------------------------------
__device__ __forceinline__ u32 smem_u32(const void* p) {
    u32 a;
    asm("{ .reg .u64 t; cvta.to.shared.u64 t, %1; cvt.u32.u64 %0, t; }" : "=r"(a) : "l"(p));
    return a;
}
__device__ __forceinline__ void cp16(u32 saddr, const void* g) {
    asm volatile("cp.async.cg.shared.global [%0], [%1], 16;" :: "r"(saddr), "l"(g));
}
__device__ __forceinline__ void ldsm4(u32& r0, u32& r1, u32& r2, u32& r3, u32 addr) {
    asm volatile("ldmatrix.sync.aligned.m8n8.x4.shared.b16 {%0,%1,%2,%3}, [%4];"
                 : "=r"(r0), "=r"(r1), "=r"(r2), "=r"(r3) : "r"(addr));
}

// ---------------- scratch (device globals) ----------------------------------
__device__ __nv_bfloat16 g_Abig[(size_t)MPAD * KT];   // [row, 384] = [hi|hi|lo]
__device__ __nv_bfloat16 g_Bbig[(size_t)HO * KT];     // [out, 384] = [hi|lo|hi]
__device__ float g_Y[(size_t)NN * HO];
__device__ float g_U[NN * H];
__device__ float g_t[NN * D];
__device__ float g_h[NN * D];
__device__ float g_agg[NN * D];
__device__ int   g_deg[NN];
__device__ float g_sum[D];
__device__ float g_sumsq[D];
__device__ int   g_rowptr[NN + 1];
__device__ int   g_cnt[NN];
__device__ int   g_adj[NE];

// ---------------- degree / CSR (built once) ---------------------------------
__global__ void deg_init_kernel() {
    int i = blockIdx.x * blockDim.x + threadIdx.x;
    if (i < NN) g_deg[i] = 1;
}
__global__ void deg_count_kernel(const int* __restrict__ ei) {
    int e = blockIdx.x * blockDim.x + threadIdx.x;
    if (e < NE) atomicAdd(&g_deg[ei[NE + e]], 1);
}
__global__ void csr_zero_kernel() {
    int i = blockIdx.x * blockDim.x + threadIdx.x;
    if (i < NN) g_cnt[i] = 0;
}
__global__ void csr_count_kernel(const int* __restrict__ ei) {
    int e = blockIdx.x * blockDim.x + threadIdx.x;
    if (e < NE) atomicAdd(&g_cnt[ei[e]], 1);
}
__global__ void csr_scan_kernel() {
    __shared__ int sh[1024];
    __shared__ int carry;
    if (threadIdx.x == 0) { carry = 0; g_rowptr[0] = 0; }
    __syncthreads();
    for (int base = 0; base < NN; base += 1024) {
        int i = base + threadIdx.x;
        int v = (i < NN) ? g_cnt[i] : 0;
        sh[threadIdx.x] = v;
        __syncthreads();
        for (int o = 1; o < 1024; o <<= 1) {
            int t = (threadIdx.x >= o) ? sh[threadIdx.x - o] : 0;
            __syncthreads();
            sh[threadIdx.x] += t;
            __syncthreads();
        }
        int base_off = carry;
        __syncthreads();
        if (i < NN) g_rowptr[i + 1] = base_off + sh[threadIdx.x];
        __syncthreads();
        if (threadIdx.x == 0) carry = base_off + sh[1023];
        __syncthreads();
    }
}
__global__ void csr_fill_kernel(const int* __restrict__ ei) {
    int e = blockIdx.x * blockDim.x + threadIdx.x;
    if (e >= NE) return;
    int s = ei[e];
    int pos = atomicAdd(&g_cnt[s], 1);
    g_adj[g_rowptr[s] + pos] = ei[NE + e];
}

// ---------------- zero agg + bn accumulators --------------------------------
__global__ void zero_kernel() {
    int i = blockIdx.x * blockDim.x + threadIdx.x;
    if (i < NN * D) g_agg[i] = 0.f;
    if (i < D) { g_sum[i] = 0.f; g_sumsq[i] = 0.f; }
}

// ---------------- input converts (bf16 double split) ------------------------
__global__ void convertx_kernel(const float* __restrict__ X) {
    int i = blockIdx.x * blockDim.x + threadIdx.x;
    if (i >= MPAD * D) return;
    int n = i >> 7, c = i & 127;
    float v = (n < NN) ? X[i] : 0.f;
    __nv_bfloat16 hi = __float2bfloat16(v);
    __nv_bfloat16 lo = __float2bfloat16(v - __bfloat162float(hi));
    size_t base = (size_t)n * KT + c;
    g_Abig[base]       = hi;
    g_Abig[base + 128] = hi;
    g_Abig[base + 256] = lo;
}
// fused BN apply + split convert (also emits fp32 g_h for u_kernel)
__global__ void bnconvert_kernel(const float* __restrict__ t,
                                 const float* __restrict__ gam,
                                 const float* __restrict__ bet) {
    int i = blockIdx.x * blockDim.x + threadIdx.x;
    if (i >= MPAD * D) return;
    int n = i >> 7, c = i & 127;
    float v = 0.f;
    if (n < NN) {
        const float invN = 1.f / (float)NN;
        float m  = g_sum[c] * invN;
        float vr = g_sumsq[c] * invN - m * m;
        v = (t[i] - m) * rsqrtf(vr + BN_EPS) * gam[c] + bet[c];
        g_h[i] = v;
    }
    __nv_bfloat16 hi = __float2bfloat16(v);
    __nv_bfloat16 lo = __float2bfloat16(v - __bfloat162float(hi));
    size_t base = (size_t)n * KT + c;
    g_Abig[base]       = hi;
    g_Abig[base + 128] = hi;
    g_Abig[base + 256] = lo;
}
__global__ void convertw_kernel(const float* __restrict__ W) {
    int i = blockIdx.x * blockDim.x + threadIdx.x;
    if (i >= HO * D) return;
    int o = i >> 7, c = i & 127;
    float v = W[i];
    __nv_bfloat16 hi = __float2bfloat16(v);
    __nv_bfloat16 lo = __float2bfloat16(v - __bfloat162float(hi));
    size_t base = (size_t)o * KT + c;
    g_Bbig[base]       = hi;
    g_Bbig[base + 128] = lo;
    g_Bbig[base + 256] = hi;
}

// ---------------- mma.sync GEMM: Y[m,o] = sum_k Abig[m,k]*Bbig[o,k] ---------
// grid (12, 157), 256 threads (8 warps, 2x4, warp tile 64x32).
// CTA tile M=128 N=128, K=384 in 6 chunks of 64, cp.async double-buffered.
__global__ __launch_bounds__(256, 2) void mma_y_kernel() {
    extern __shared__ char smem[];
    const int tid  = threadIdx.x;
    const int wid  = tid >> 5, lane = tid & 31;
    const int wm   = (wid >> 2) * 64;        // 0 / 64
    const int wn   = (wid & 3) * 32;         // 0/32/64/96
    const int bm   = blockIdx.y * 128;
    const int bo   = blockIdx.x * 128;
    const int g    = lane >> 2;
    const int tq   = lane & 3;

    const u32 sb = smem_u32(smem);

    float acc[4][4][4];
#pragma unroll
    for (int i = 0; i < 4; i++)
#pragma unroll
        for (int j = 0; j < 4; j++)
#pragma unroll
            for (int q = 0; q < 4; q++) acc[i][j][q] = 0.f;

    // loaders: 2 threads per tile row, 4x16B each per matrix per chunk
    const int lr  = tid >> 1;                 // 0..127
    const int lcb = (tid & 1) * 64;           // byte offset 0 / 64
    const char* gA = (const char*)g_Abig + (size_t)(bm + lr) * (KT * 2) + lcb;
    const char* gB = (const char*)g_Bbig + (size_t)(bo + lr) * (KT * 2) + lcb;
    const u32 sA  = sb + lr * ROWB + lcb;
    const u32 sBo = sb + ATILE + lr * ROWB + lcb;

    // prologue: chunk 0 -> buffer 0
#pragma unroll
    for (int j = 0; j < 4; j++) {
        cp16(sA  + j * 16, gA + j * 16);
        cp16(sBo + j * 16, gB + j * 16);
    }
    asm volatile("cp.async.commit_group;");

    // ldmatrix lane addressing
    const int a_row = wm + (lane & 15);
    const int a_kb  = (lane >> 4) * 16;          // +0 / +16 bytes
    const int b_t   = lane >> 3;
    const int b_row = wn + ((b_t >> 1) * 8) + (lane & 7);
    const int b_kb  = (b_t & 1) * 16;

    for (int ch = 0; ch < 6; ch++) {
        if (ch < 5) {
            const u32 base = ((ch + 1) & 1) * BUFB;
            const int off = (ch + 1) * 128;
#pragma unroll
            for (int j = 0; j < 4; j++) {
                cp16(base + sA  + j * 16, gA + off + j * 16);
                cp16(base + sBo + j * 16, gB + off + j * 16);
            }
            asm volatile("cp.async.commit_group;");
            asm volatile("cp.async.wait_group 1;");
        } else {
            asm volatile("cp.async.wait_group 0;");
        }
        __syncthreads();

        const u32 Ab = sb + (ch & 1) * BUFB;
        const u32 Bb = Ab + ATILE;
#pragma unroll
        for (int k = 0; k < 4; k++) {
            const int kb = k * 32;               // 16 bf16 = 32 bytes
            u32 a[4][4], b[2][4];
#pragma unroll
            for (int i = 0; i < 4; i++)
                ldsm4(a[i][0], a[i][1], a[i][2], a[i][3],
                      Ab + (a_row + i * 16) * ROWB + kb + a_kb);
#pragma unroll
            for (int jj = 0; jj < 2; jj++)
                ldsm4(b[jj][0], b[jj][1], b[jj][2], b[jj][3],
                      Bb + (b_row + jj * 16) * ROWB + kb + b_kb);
#pragma unroll
            for (int i = 0; i < 4; i++)
#pragma unroll
                for (int j = 0; j < 4; j++) {
                    const u32 b0 = b[j >> 1][(j & 1) * 2];
                    const u32 b1 = b[j >> 1][(j & 1) * 2 + 1];
                    asm volatile(
                        "mma.sync.aligned.m16n8k16.row.col.f32.bf16.bf16.f32 "
                        "{%0,%1,%2,%3}, {%4,%5,%6,%7}, {%8,%9}, {%0,%1,%2,%3};"
                        : "+f"(acc[i][j][0]), "+f"(acc[i][j][1]),
                          "+f"(acc[i][j][2]), "+f"(acc[i][j][3])
                        : "r"(a[i][0]), "r"(a[i][1]), "r"(a[i][2]), "r"(a[i][3]),
                          "r"(b0), "r"(b1));
                }
        }
        __syncthreads();
    }

    // epilogue
#pragma unroll
    for (int i = 0; i < 4; i++) {
        int r0 = bm + wm + i * 16 + g;
        int r1 = r0 + 8;
#pragma unroll
        for (int j = 0; j < 4; j++) {
            int col = bo + wn + j * 8 + tq * 2;
            if (r0 < NN)
                *(float2*)(g_Y + (size_t)r0 * HO + col) = make_float2(acc[i][j][0], acc[i][j][1]);
            if (r1 < NN)
                *(float2*)(g_Y + (size_t)r1 * HO + col) = make_float2(acc[i][j][2], acc[i][j][3]);
        }
    }
}

// ---------------- U[n,h] = sum_k X[n,k]*Wu[h,k]  (warp per node) ------------
__global__ void u_kernel(const float* __restrict__ X, const float* __restrict__ Wu, int M) {
    __shared__ float wu[H * D];
    for (int i = threadIdx.x; i < H * D; i += blockDim.x) wu[i] = Wu[i];
    __syncthreads();
    int warp = blockIdx.x * (blockDim.x >> 5) + (threadIdx.x >> 5);
    int lane = threadIdx.x & 31;
    if (warp >= M) return;
    const float* xr = X + (size_t)warp * D;
    float x0 = xr[lane], x1 = xr[lane + 32], x2 = xr[lane + 64], x3 = xr[lane + 96];
#pragma unroll
    for (int h = 0; h < H; h++) {
        float p = x0 * wu[h * D + lane] + x1 * wu[h * D + lane + 32]
                + x2 * wu[h * D + lane + 64] + x3 * wu[h * D + lane + 96];
#pragma unroll
        for (int o = 16; o; o >>= 1) p += __shfl_xor_sync(0xffffffffu, p, o);
        if (lane == 0) g_U[warp * H + h] = p;
    }
}

// ---------------- scatter: warp per SRC node, Y row in registers ------------
__global__ __launch_bounds__(256) void scatter_kernel(const float* __restrict__ cvec) {
    int warp = blockIdx.x * 8 + (threadIdx.x >> 5);
    int lane = threadIdx.x & 31;
    if (warp >= NN) return;
    const int s = warp;

    F4U yv[H];
    const float4* y4 = reinterpret_cast<const float4*>(g_Y + (size_t)s * HO) + lane;
#pragma unroll
    for (int h = 0; h < H; h++) yv[h].f = y4[h * 32];

    float us = 0.f, cl = 0.f;
    if (lane < H) { us = g_U[s * H + lane]; cl = __ldg(&cvec[lane]); }

    int row = g_rowptr[s], end = g_rowptr[s + 1];
    for (int i = row - 1; i < end; i++) {     // i == row-1 encodes the self loop
        int d = s;
        float ud = us;
        if (i >= row) {
            d = g_adj[i];
            ud = (lane < H) ? __ldg(&g_U[d * H + lane]) : 0.f;
        }
        float logit = (lane < H) ? (ud - us + cl) : -1e30f;
        float m = logit;
#pragma unroll
        for (int o = 16; o; o >>= 1) m = fmaxf(m, __shfl_xor_sync(0xffffffffu, m, o));
        float e = (lane < H) ? __expf(logit - m) : 0.f;
        float ss = e;
#pragma unroll
        for (int o = 16; o; o >>= 1) ss += __shfl_xor_sync(0xffffffffu, ss, o);
        float a = e / ss;

        u64 m0 = 0ull, m1 = 0ull;
#pragma unroll
        for (int h = 0; h < H; h++) {
            float ah = __shfl_sync(0xffffffffu, a, h);
            u64 a2 = pack2(ah, ah);
            m0 = ffma2(a2, yv[h].u[0], m0);
            m1 = ffma2(a2, yv[h].u[1], m1);
        }
        float r0, r1, r2, r3;
        unpack2(m0, r0, r1);
        unpack2(m1, r2, r3);
        red_add_v4(g_agg + (size_t)d * D + lane * 4, r0, r1, r2, r3);
    }
}

// ---------------- finalize: out = agg/deg + b (+relu, + BN stats) -----------
__global__ __launch_bounds__(256) void finalize_kernel(const float* __restrict__ bvec,
                                                       float* __restrict__ out,
                                                       int relu, int do_stats) {
    int c = threadIdx.x & 127;
    float bb = __ldg(&bvec[c]);
    float lsum = 0.f, lsq = 0.f;
    for (int i = blockIdx.x * blockDim.x + threadIdx.x; i < NN * D;
         i += gridDim.x * blockDim.x) {
        float v = g_agg[i] / (float)g_deg[i >> 7] + bb;
        if (relu) v = fmaxf(v, 0.f);
        out[i] = v;
        lsum += v; lsq += v * v;
    }
    if (do_stats) {
        __shared__ float s1[256], s2[256];
        s1[threadIdx.x] = lsum; s2[threadIdx.x] = lsq;
        __syncthreads();
        if (threadIdx.x < 128) {
            atomicAdd(&g_sum[threadIdx.x],   s1[threadIdx.x] + s1[threadIdx.x + 128]);
            atomicAdd(&g_sumsq[threadIdx.x], s2[threadIdx.x] + s2[threadIdx.x + 128]);
        }
    }
}

// ---------------- launch ----------------------------------------------------
static void launch_mma() {
    cudaFuncSetAttribute(mma_y_kernel, cudaFuncAttributeMaxDynamicSharedMemorySize, SMEM_DYN);
    mma_y_kernel<<<dim3(12, 157), 256, SMEM_DYN>>>();
}

extern "C" void kernel_launch(void* const* d_in, const int* in_sizes, int n_in,
                              void* d_out, int out_size)
{
    const float* x  = (const float*)d_in[0];
    const int*   ei = (const int*)d_in[1];

    const float *Wlin[3], *Wu[3], *cv[3], *bv[3], *bng[2], *bnb[2];
    if (in_sizes[6] == H * D * D) {
        for (int l = 0; l < 3; l++) {
            Wlin[l] = (const float*)d_in[2 + 4 * l];
            Wu[l]   = (const float*)d_in[3 + 4 * l];
            cv[l]   = (const float*)d_in[4 + 4 * l];
            bv[l]   = (const float*)d_in[5 + 4 * l];
        }
        bng[0] = (const float*)d_in[14]; bnb[0] = (const float*)d_in[15];
        bng[1] = (const float*)d_in[16]; bnb[1] = (const float*)d_in[17];
    } else {
        Wlin[0] = (const float*)d_in[2];  Wu[0] = (const float*)d_in[3];
        cv[0]   = (const float*)d_in[4];  bv[0] = (const float*)d_in[5];
        bng[0]  = (const float*)d_in[6];  bnb[0] = (const float*)d_in[7];
        Wlin[1] = (const float*)d_in[8];  Wu[1] = (const float*)d_in[9];
        cv[1]   = (const float*)d_in[10]; bv[1] = (const float*)d_in[11];
        bng[1]  = (const float*)d_in[12]; bnb[1] = (const float*)d_in[13];
        Wlin[2] = (const float*)d_in[14]; Wu[2] = (const float*)d_in[15];
        cv[2]   = (const float*)d_in[16]; bv[2] = (const float*)d_in[17];
    }

    float* out = (float*)d_out;
    float* t = nullptr; float* hbuf = nullptr;
    cudaGetSymbolAddress((void**)&t, g_t);
    cudaGetSymbolAddress((void**)&hbuf, g_h);

    const int NCONV = (MPAD * D + 255) / 256;
    const int WCONV = (HO * D + 255) / 256;

    // ---- layer 0 front, ordered so launch index 3 == mma_y (ncu -s window) ----
    convertx_kernel<<<NCONV, 256>>>(x);                       // 0
    convertw_kernel<<<WCONV, 256>>>(Wlin[0]);                 // 1
    deg_init_kernel<<<(NN + 255) / 256, 256>>>();             // 2
    launch_mma();                                             // 3  <- profiled
    deg_count_kernel<<<(NE + 255) / 256, 256>>>(ei);
    csr_zero_kernel<<<(NN + 255) / 256, 256>>>();
    csr_count_kernel<<<(NE + 255) / 256, 256>>>(ei);
    csr_scan_kernel<<<1, 1024>>>();
    csr_zero_kernel<<<(NN + 255) / 256, 256>>>();
    csr_fill_kernel<<<(NE + 255) / 256, 256>>>(ei);

    u_kernel<<<(NN * 32 + 255) / 256, 256>>>(x, Wu[0], NN);
    zero_kernel<<<(NN * D + 255) / 256, 256>>>();
    scatter_kernel<<<(NN + 7) / 8, 256>>>(cv[0]);
    finalize_kernel<<<192, 256>>>(bv[0], t, 1, 1);

    // ---- layer 1 (BN0 fused into convert) ----
    bnconvert_kernel<<<NCONV, 256>>>(t, bng[0], bnb[0]);
    convertw_kernel<<<WCONV, 256>>>(Wlin[1]);
    launch_mma();
    u_kernel<<<(NN * 32 + 255) / 256, 256>>>(hbuf, Wu[1], NN);
    zero_kernel<<<(NN * D + 255) / 256, 256>>>();
    scatter_kernel<<<(NN + 7) / 8, 256>>>(cv[1]);
    finalize_kernel<<<192, 256>>>(bv[1], t, 1, 1);

    // ---- layer 2 (BN1 fused; no relu/stats) -> d_out ----
    bnconvert_kernel<<<NCONV, 256>>>(t, bng[1], bnb[1]);
    convertw_kernel<<<WCONV, 256>>>(Wlin[2]);
    launch_mma();
    u_kernel<<<(NN * 32 + 255) / 256, 256>>>(hbuf, Wu[2], NN);
    zero_kernel<<<(NN * D + 255) / 256, 256>>>();
    scatter_kernel<<<(NN + 7) / 8, 256>>>(cv[2]);
    finalize_kernel<<<192, 256>>>(bv[2], out, 0, 0);
}

// round 9
// speedup vs baseline: 1.1999x; 1.1280x over previous
#include <cuda_runtime.h>
#include <cuda_bf16.h>
#include <math.h>
#include <cstdint>

#define NN 20000
#define NE 320000
#define D  128
#define H  12
#define HO 1536          // H * D
#define BN_EPS 1e-5f
#define MPAD 20096       // 157 * 128
#define KTA 256          // [hi|lo] storage, logical K=384 via chunk reuse

// mma smem: rows of 64 bf16 data + 16B pad = 144 B -> LDSM conflict-free
#define ROWB   144
#define BCH    (256 * ROWB)          // 36864 B  (B chunk: 256 rows)
#define ACH    (128 * ROWB)          // 18432 B  (A chunk: 128 rows)
#define SMEM_MMA (4 * BCH + 4 * ACH) // 221184 B

typedef unsigned long long u64;
typedef uint32_t u32;

// ---------------- packed f32x2 helpers --------------------------------------
__device__ __forceinline__ u64 pack2(float lo, float hi) {
    u64 r; asm("mov.b64 %0, {%1,%2};" : "=l"(r) : "f"(lo), "f"(hi)); return r;
}
__device__ __forceinline__ u64 ffma2(u64 a, u64 b, u64 c) {
    u64 d; asm("fma.rn.f32x2 %0, %1, %2, %3;" : "=l"(d) : "l"(a), "l"(b), "l"(c)); return d;
}
__device__ __forceinline__ void unpack2(u64 v, float& lo, float& hi) {
    asm("mov.b64 {%0,%1}, %2;" : "=f"(lo), "=f"(hi) : "l"(v));
}
__device__ __forceinline__ void red_add_v4(float* p, float a, float b, float c, float d) {
    asm volatile("red.global.add.v4.f32 [%0], {%1,%2,%3,%4};"
                 :: "l"(p), "f"(a), "f"(b), "f"(c), "f"(d) : "memory");
}
union F4U { float4 f; u64 u[2]; };

// ---------------- mma building blocks ---------------------------------------
__device__ __forceinline__ u32 smem_u32(const void* p) {
    u32 a;
    asm("{ .reg .u64 t; cvta.to.shared.u64 t, %1; cvt.u32.u64 %0, t; }" : "=r"(a) : "l"(p));
    return a;
}
__device__ __forceinline__ void cp16(u32 saddr, const void* g) {
    asm volatile("cp.async.cg.shared.global [%0], [%1], 16;" :: "r"(saddr), "l"(g));
}
__device__ __forceinline__ void ldsm4(u32& r0, u32& r1, u32& r2, u32& r3, u32 addr) {
    asm volatile("ldmatrix.sync.aligned.m8n8.x4.shared.b16 {%0,%1,%2,%3}, [%4];"
                 : "=r"(r0), "=r"(r1), "=r"(r2), "=r"(r3) : "r"(addr));
}

// ---------------- scratch (device globals) ----------------------------------
__device__ __nv_bfloat16 g_Abig[(size_t)MPAD * KTA];  // [row, 256] = [hi|lo]
__device__ __nv_bfloat16 g_Bbig[(size_t)HO * KTA];    // [out, 256] = [hi|lo]
__device__ float g_Y[(size_t)NN * HO];
__device__ float g_U[NN * H];
__device__ float g_t[NN * D];
__device__ float g_h[NN * D];
__device__ float g_agg[NN * D];
__device__ int   g_deg[NN];
__device__ float g_sum[D];
__device__ float g_sumsq[D];
__device__ int   g_rowptr[NN + 1];
__device__ int   g_cnt[NN];
__device__ int   g_adj[NE];

// ---------------- degree / CSR (built once) ---------------------------------
__global__ void deg_init_kernel() {
    int i = blockIdx.x * blockDim.x + threadIdx.x;
    if (i < NN) g_deg[i] = 1;
}
__global__ void deg_count_kernel(const int* __restrict__ ei) {
    int e = blockIdx.x * blockDim.x + threadIdx.x;
    if (e < NE) atomicAdd(&g_deg[ei[NE + e]], 1);
}
__global__ void csr_zero_kernel() {
    int i = blockIdx.x * blockDim.x + threadIdx.x;
    if (i < NN) g_cnt[i] = 0;
}
__global__ void csr_count_kernel(const int* __restrict__ ei) {
    int e = blockIdx.x * blockDim.x + threadIdx.x;
    if (e < NE) atomicAdd(&g_cnt[ei[e]], 1);
}
__global__ void csr_scan_kernel() {
    __shared__ int sh[1024];
    __shared__ int carry;
    if (threadIdx.x == 0) { carry = 0; g_rowptr[0] = 0; }
    __syncthreads();
    for (int base = 0; base < NN; base += 1024) {
        int i = base + threadIdx.x;
        int v = (i < NN) ? g_cnt[i] : 0;
        sh[threadIdx.x] = v;
        __syncthreads();
        for (int o = 1; o < 1024; o <<= 1) {
            int t = (threadIdx.x >= o) ? sh[threadIdx.x - o] : 0;
            __syncthreads();
            sh[threadIdx.x] += t;
            __syncthreads();
        }
        int base_off = carry;
        __syncthreads();
        if (i < NN) g_rowptr[i + 1] = base_off + sh[threadIdx.x];
        __syncthreads();
        if (threadIdx.x == 0) carry = base_off + sh[1023];
        __syncthreads();
    }
}
__global__ void csr_fill_kernel(const int* __restrict__ ei) {
    int e = blockIdx.x * blockDim.x + threadIdx.x;
    if (e >= NE) return;
    int s = ei[e];
    int pos = atomicAdd(&g_cnt[s], 1);
    g_adj[g_rowptr[s] + pos] = ei[NE + e];
}

// ---------------- zero agg + bn accumulators --------------------------------
__global__ void zero_kernel() {
    int i = blockIdx.x * blockDim.x + threadIdx.x;
    if (i < NN * D) g_agg[i] = 0.f;
    if (i < D) { g_sum[i] = 0.f; g_sumsq[i] = 0.f; }
}

// ---------------- input converts (bf16 double split, [hi|lo]) ---------------
__global__ void convertx_kernel(const float* __restrict__ X) {
    int i = blockIdx.x * blockDim.x + threadIdx.x;
    if (i >= MPAD * D) return;
    int n = i >> 7, c = i & 127;
    float v = (n < NN) ? X[i] : 0.f;
    __nv_bfloat16 hi = __float2bfloat16(v);
    __nv_bfloat16 lo = __float2bfloat16(v - __bfloat162float(hi));
    size_t base = (size_t)n * KTA + c;
    g_Abig[base]       = hi;
    g_Abig[base + 128] = lo;
}
__global__ void bnconvert_kernel(const float* __restrict__ t,
                                 const float* __restrict__ gam,
                                 const float* __restrict__ bet) {
    int i = blockIdx.x * blockDim.x + threadIdx.x;
    if (i >= MPAD * D) return;
    int n = i >> 7, c = i & 127;
    float v = 0.f;
    if (n < NN) {
        const float invN = 1.f / (float)NN;
        float m  = g_sum[c] * invN;
        float vr = g_sumsq[c] * invN - m * m;
        v = (t[i] - m) * rsqrtf(vr + BN_EPS) * gam[c] + bet[c];
        g_h[i] = v;
    }
    __nv_bfloat16 hi = __float2bfloat16(v);
    __nv_bfloat16 lo = __float2bfloat16(v - __bfloat162float(hi));
    size_t base = (size_t)n * KTA + c;
    g_Abig[base]       = hi;
    g_Abig[base + 128] = lo;
}
__global__ void convertw_kernel(const float* __restrict__ W) {
    int i = blockIdx.x * blockDim.x + threadIdx.x;
    if (i >= HO * D) return;
    int o = i >> 7, c = i & 127;
    float v = W[i];
    __nv_bfloat16 hi = __float2bfloat16(v);
    __nv_bfloat16 lo = __float2bfloat16(v - __bfloat162float(hi));
    size_t base = (size_t)o * KTA + c;
    g_Bbig[base]       = hi;
    g_Bbig[base + 128] = lo;
}

// ---------------- B-resident mma GEMM ---------------------------------------
// grid (6, 24), 512 threads (16 warps, 4x4, warp tile 32x64).
// Each CTA: one 256-wide N column, B (4 chunks of K64) resident in smem;
// sweeps bm tiles (M=128). Logical K-schedule (3-term split, K=384):
//   step: 0     1     2     3     4     5
//   A  :  hi0   hi1   hi0   hi1   lo0   lo1     (buffers 0,1,0,1,2,3)
//   B  :  hi0   hi1   lo0   lo1   hi0   hi1     (chunks  0,1,2,3,0,1)
__global__ void __launch_bounds__(512, 1) mma_y_kernel() {
    extern __shared__ char smem[];
    const u32 sb = smem_u32(smem);
    const int tid = threadIdx.x, wid = tid >> 5, lane = tid & 31;
    const int wm = (wid >> 2) * 32;
    const int wn = (wid & 3) * 64;
    const int bo = blockIdx.x * 256;
    const int g  = lane >> 2, tq = lane & 3;

    const u32 sB = sb;
    const u32 sA = sb + 4 * BCH;

    // ldmatrix lane addressing (proven layout from R5/R7)
    const int a_row = wm + (lane & 15);
    const int a_kb  = (lane >> 4) * 16;
    const int b_t   = lane >> 3;
    const int b_row = wn + ((b_t >> 1) * 8) + (lane & 7);
    const int b_kb  = (b_t & 1) * 16;

    // --- load B resident (4 chunks x 256 rows x 128 B) ---
    {
        const int r = tid >> 1, hb = (tid & 1) * 64;
        const char* gB = (const char*)g_Bbig + (size_t)(bo + r) * (KTA * 2) + hb;
#pragma unroll
        for (int c = 0; c < 4; c++) {
            u32 dst = sB + c * BCH + r * ROWB + hb;
            const char* src = gB + c * 128;
#pragma unroll
            for (int j = 0; j < 4; j++) cp16(dst + j * 16, src + j * 16);
        }
    }

    // A loader: thread -> (row = tid>>2, quarter = (tid&3)*32 B), 2x cp16
    const int ar = tid >> 2;
    const int aq = (tid & 3) * 32;
    auto loadA = [&](int buf, int bm, int coff) {
        const char* src = (const char*)g_Abig + (size_t)(bm + ar) * (KTA * 2) + coff + aq;
        u32 dst = sA + buf * ACH + ar * ROWB + aq;
        cp16(dst, src);
        cp16(dst + 16, src + 16);
    };

    // prologue: B + hi(tile0) in one group
    const int bm0 = blockIdx.y * 128;
    loadA(0, bm0, 0);
    loadA(1, bm0, 128);
    asm volatile("cp.async.commit_group;");

    float acc[2][8][4];

    auto stepK = [&](u32 Ab, u32 Bb) {
#pragma unroll
        for (int k = 0; k < 4; k++) {
            const int kb = k * 32;
            u32 a[2][4], b[4][4];
#pragma unroll
            for (int i = 0; i < 2; i++)
                ldsm4(a[i][0], a[i][1], a[i][2], a[i][3],
                      Ab + (a_row + i * 16) * ROWB + kb + a_kb);
#pragma unroll
            for (int jj = 0; jj < 4; jj++)
                ldsm4(b[jj][0], b[jj][1], b[jj][2], b[jj][3],
                      Bb + (b_row + jj * 16) * ROWB + kb + b_kb);
#pragma unroll
            for (int i = 0; i < 2; i++)
#pragma unroll
                for (int j = 0; j < 8; j++) {
                    const u32 b0 = b[j >> 1][(j & 1) * 2];
                    const u32 b1 = b[j >> 1][(j & 1) * 2 + 1];
                    asm volatile(
                        "mma.sync.aligned.m16n8k16.row.col.f32.bf16.bf16.f32 "
                        "{%0,%1,%2,%3}, {%4,%5,%6,%7}, {%8,%9}, {%0,%1,%2,%3};"
                        : "+f"(acc[i][j][0]), "+f"(acc[i][j][1]),
                          "+f"(acc[i][j][2]), "+f"(acc[i][j][3])
                        : "r"(a[i][0]), "r"(a[i][1]), "r"(a[i][2]), "r"(a[i][3]),
                          "r"(b0), "r"(b1));
                }
        }
    };

    for (int tmi = blockIdx.y; tmi < 157; tmi += 24) {
        const int bm = tmi * 128;
#pragma unroll
        for (int i = 0; i < 2; i++)
#pragma unroll
            for (int j = 0; j < 8; j++)
#pragma unroll
                for (int q = 0; q < 4; q++) acc[i][j][q] = 0.f;

        __syncthreads();                          // lo buffers free of prev readers
        loadA(2, bm, 256);                        // stream lo(t)
        loadA(3, bm, 384);
        asm volatile("cp.async.commit_group;");
        asm volatile("cp.async.wait_group 1;");   // hi(t) (+B first time) ready
        __syncthreads();

        stepK(sA + 0 * ACH, sB + 0 * BCH);        // hi0 x B_hi0
        stepK(sA + 1 * ACH, sB + 1 * BCH);        // hi1 x B_hi1
        stepK(sA + 0 * ACH, sB + 2 * BCH);        // hi0 x B_lo0
        stepK(sA + 1 * ACH, sB + 3 * BCH);        // hi1 x B_lo1

        __syncthreads();                          // hi reads complete
        const int nt = tmi + 24;
        if (nt < 157) {
            loadA(0, nt * 128, 0);                // prefetch hi(t+1)
            loadA(1, nt * 128, 128);
            asm volatile("cp.async.commit_group;");
            asm volatile("cp.async.wait_group 1;"); // lo(t) ready
        } else {
            asm volatile("cp.async.wait_group 0;");
        }
        __syncthreads();

        stepK(sA + 2 * ACH, sB + 0 * BCH);        // lo0 x B_hi0
        stepK(sA + 3 * ACH, sB + 1 * BCH);        // lo1 x B_hi1

        // epilogue
#pragma unroll
        for (int i = 0; i < 2; i++) {
            int r0 = bm + wm + i * 16 + g;
            int r1 = r0 + 8;
#pragma unroll
            for (int j = 0; j < 8; j++) {
                int col = bo + wn + j * 8 + tq * 2;
                if (r0 < NN)
                    *(float2*)(g_Y + (size_t)r0 * HO + col) =
                        make_float2(acc[i][j][0], acc[i][j][1]);
                if (r1 < NN)
                    *(float2*)(g_Y + (size_t)r1 * HO + col) =
                        make_float2(acc[i][j][2], acc[i][j][3]);
            }
        }
    }
}

// ---------------- U[n,h] = sum_k X[n,k]*Wu[h,k]  (warp per node) ------------
__global__ void u_kernel(const float* __restrict__ X, const float* __restrict__ Wu, int M) {
    __shared__ float wu[H * D];
    for (int i = threadIdx.x; i < H * D; i += blockDim.x) wu[i] = Wu[i];
    __syncthreads();
    int warp = blockIdx.x * (blockDim.x >> 5) + (threadIdx.x >> 5);
    int lane = threadIdx.x & 31;
    if (warp >= M) return;
    const float* xr = X + (size_t)warp * D;
    float x0 = xr[lane], x1 = xr[lane + 32], x2 = xr[lane + 64], x3 = xr[lane + 96];
#pragma unroll
    for (int h = 0; h < H; h++) {
        float p = x0 * wu[h * D + lane] + x1 * wu[h * D + lane + 32]
                + x2 * wu[h * D + lane + 64] + x3 * wu[h * D + lane + 96];
#pragma unroll
        for (int o = 16; o; o >>= 1) p += __shfl_xor_sync(0xffffffffu, p, o);
        if (lane == 0) g_U[warp * H + h] = p;
    }
}

// ---------------- scatter: warp per SRC node, Y row in registers ------------
__global__ __launch_bounds__(256) void scatter_kernel(const float* __restrict__ cvec) {
    int warp = blockIdx.x * 8 + (threadIdx.x >> 5);
    int lane = threadIdx.x & 31;
    if (warp >= NN) return;
    const int s = warp;

    F4U yv[H];
    const float4* y4 = reinterpret_cast<const float4*>(g_Y + (size_t)s * HO) + lane;
#pragma unroll
    for (int h = 0; h < H; h++) yv[h].f = y4[h * 32];

    float us = 0.f, cl = 0.f;
    if (lane < H) { us = g_U[s * H + lane]; cl = __ldg(&cvec[lane]); }

    int row = g_rowptr[s], end = g_rowptr[s + 1];
    for (int i = row - 1; i < end; i++) {     // i == row-1 encodes the self loop
        int d = s;
        float ud = us;
        if (i >= row) {
            d = g_adj[i];
            ud = (lane < H) ? __ldg(&g_U[d * H + lane]) : 0.f;
        }
        float logit = (lane < H) ? (ud - us + cl) : -1e30f;
        float m = logit;
#pragma unroll
        for (int o = 16; o; o >>= 1) m = fmaxf(m, __shfl_xor_sync(0xffffffffu, m, o));
        float e = (lane < H) ? __expf(logit - m) : 0.f;
        float ss = e;
#pragma unroll
        for (int o = 16; o; o >>= 1) ss += __shfl_xor_sync(0xffffffffu, ss, o);
        float a = e / ss;

        u64 m0 = 0ull, m1 = 0ull;
#pragma unroll
        for (int h = 0; h < H; h++) {
            float ah = __shfl_sync(0xffffffffu, a, h);
            u64 a2 = pack2(ah, ah);
            m0 = ffma2(a2, yv[h].u[0], m0);
            m1 = ffma2(a2, yv[h].u[1], m1);
        }
        float r0, r1, r2, r3;
        unpack2(m0, r0, r1);
        unpack2(m1, r2, r3);
        red_add_v4(g_agg + (size_t)d * D + lane * 4, r0, r1, r2, r3);
    }
}

// ---------------- finalize: out = agg/deg + b (+relu, + BN stats) -----------
__global__ __launch_bounds__(256) void finalize_kernel(const float* __restrict__ bvec,
                                                       float* __restrict__ out,
                                                       int relu, int do_stats) {
    int c = threadIdx.x & 127;
    float bb = __ldg(&bvec[c]);
    float lsum = 0.f, lsq = 0.f;
    for (int i = blockIdx.x * blockDim.x + threadIdx.x; i < NN * D;
         i += gridDim.x * blockDim.x) {
        float v = g_agg[i] / (float)g_deg[i >> 7] + bb;
        if (relu) v = fmaxf(v, 0.f);
        out[i] = v;
        lsum += v; lsq += v * v;
    }
    if (do_stats) {
        __shared__ float s1[256], s2[256];
        s1[threadIdx.x] = lsum; s2[threadIdx.x] = lsq;
        __syncthreads();
        if (threadIdx.x < 128) {
            atomicAdd(&g_sum[threadIdx.x],   s1[threadIdx.x] + s1[threadIdx.x + 128]);
            atomicAdd(&g_sumsq[threadIdx.x], s2[threadIdx.x] + s2[threadIdx.x + 128]);
        }
    }
}

// ---------------- launch ----------------------------------------------------
static void launch_mma() {
    cudaFuncSetAttribute(mma_y_kernel, cudaFuncAttributeMaxDynamicSharedMemorySize, SMEM_MMA);
    mma_y_kernel<<<dim3(6, 24), 512, SMEM_MMA>>>();
}

extern "C" void kernel_launch(void* const* d_in, const int* in_sizes, int n_in,
                              void* d_out, int out_size)
{
    const float* x  = (const float*)d_in[0];
    const int*   ei = (const int*)d_in[1];

    const float *Wlin[3], *Wu[3], *cv[3], *bv[3], *bng[2], *bnb[2];
    if (in_sizes[6] == H * D * D) {
        for (int l = 0; l < 3; l++) {
            Wlin[l] = (const float*)d_in[2 + 4 * l];
            Wu[l]   = (const float*)d_in[3 + 4 * l];
            cv[l]   = (const float*)d_in[4 + 4 * l];
            bv[l]   = (const float*)d_in[5 + 4 * l];
        }
        bng[0] = (const float*)d_in[14]; bnb[0] = (const float*)d_in[15];
        bng[1] = (const float*)d_in[16]; bnb[1] = (const float*)d_in[17];
    } else {
        Wlin[0] = (const float*)d_in[2];  Wu[0] = (const float*)d_in[3];
        cv[0]   = (const float*)d_in[4];  bv[0] = (const float*)d_in[5];
        bng[0]  = (const float*)d_in[6];  bnb[0] = (const float*)d_in[7];
        Wlin[1] = (const float*)d_in[8];  Wu[1] = (const float*)d_in[9];
        cv[1]   = (const float*)d_in[10]; bv[1] = (const float*)d_in[11];
        bng[1]  = (const float*)d_in[12]; bnb[1] = (const float*)d_in[13];
        Wlin[2] = (const float*)d_in[14]; Wu[2] = (const float*)d_in[15];
        cv[2]   = (const float*)d_in[16]; bv[2] = (const float*)d_in[17];
    }

    float* out = (float*)d_out;
    float* t = nullptr; float* hbuf = nullptr;
    cudaGetSymbolAddress((void**)&t, g_t);
    cudaGetSymbolAddress((void**)&hbuf, g_h);

    const int NCONV = (MPAD * D + 255) / 256;
    const int WCONV = (HO * D + 255) / 256;

    // ---- layer 0 front, ordered so launch index 3 == mma_y (ncu -s window) ----
    convertx_kernel<<<NCONV, 256>>>(x);                       // 0
    convertw_kernel<<<WCONV, 256>>>(Wlin[0]);                 // 1
    deg_init_kernel<<<(NN + 255) / 256, 256>>>();             // 2
    launch_mma();                                             // 3  <- profiled
    deg_count_kernel<<<(NE + 255) / 256, 256>>>(ei);
    csr_zero_kernel<<<(NN + 255) / 256, 256>>>();
    csr_count_kernel<<<(NE + 255) / 256, 256>>>(ei);
    csr_scan_kernel<<<1, 1024>>>();
    csr_zero_kernel<<<(NN + 255) / 256, 256>>>();
    csr_fill_kernel<<<(NE + 255) / 256, 256>>>(ei);

    u_kernel<<<(NN * 32 + 255) / 256, 256>>>(x, Wu[0], NN);
    zero_kernel<<<(NN * D + 255) / 256, 256>>>();
    scatter_kernel<<<(NN + 7) / 8, 256>>>(cv[0]);
    finalize_kernel<<<192, 256>>>(bv[0], t, 1, 1);

    // ---- layer 1 (BN0 fused into convert) ----
    bnconvert_kernel<<<NCONV, 256>>>(t, bng[0], bnb[0]);
    convertw_kernel<<<WCONV, 256>>>(Wlin[1]);
    launch_mma();
    u_kernel<<<(NN * 32 + 255) / 256, 256>>>(hbuf, Wu[1], NN);
    zero_kernel<<<(NN * D + 255) / 256, 256>>>();
    scatter_kernel<<<(NN + 7) / 8, 256>>>(cv[1]);
    finalize_kernel<<<192, 256>>>(bv[1], t, 1, 1);

    // ---- layer 2 (BN1 fused; no relu/stats) -> d_out ----
    bnconvert_kernel<<<NCONV, 256>>>(t, bng[1], bnb[1]);
    convertw_kernel<<<WCONV, 256>>>(Wlin[2]);
    launch_mma();
    u_kernel<<<(NN * 32 + 255) / 256, 256>>>(hbuf, Wu[2], NN);
    zero_kernel<<<(NN * D + 255) / 256, 256>>>();
    scatter_kernel<<<(NN + 7) / 8, 256>>>(cv[2]);
    finalize_kernel<<<192, 256>>>(bv[2], out, 0, 0);
}